// round 14
// baseline (speedup 1.0000x reference)
#include <cuda_runtime.h>
#include <cuda_fp16.h>
#include <cstdint>
#include <cstddef>

// Problem constants (fixed: N_VERT=2048, NF=8, order=16, LMAX=2 -> a1=a2=1)
constexpr int    N      = 2048;
constexpr size_t NN     = (size_t)N * N;
constexpr int    NFILT  = 8;
constexpr int    NCOEF  = 17;
constexpr double PI     = 3.14159265358979323846;

// fp32 archive T_0..T_16 (for the final reduction)
__device__ float  g_scratch[(size_t)17 * NN];
// fp16 hi/lo operand arrays: MH | ML | H0 | L0 | H1 | L1
constexpr size_t HOFF_MH = 0;
constexpr size_t HOFF_ML = NN;
constexpr size_t HOFF_H0 = 2 * NN;
constexpr size_t HOFF_L0 = 3 * NN;
constexpr size_t HOFF_H1 = 4 * NN;
constexpr size_t HOFF_L1 = 5 * NN;
__device__ __half g_half[(size_t)6 * NN];
__device__ float  g_c[NCOEF * NFILT];

// ---------------------------------------------------------------------------
// helpers
// ---------------------------------------------------------------------------
__device__ __forceinline__ uint32_t smem_to_u32(const void* p) {
    uint32_t a;
    asm("{ .reg .u64 t; cvta.to.shared.u64 t, %1; cvt.u32.u64 %0, t; }" : "=r"(a) : "l"(p));
    return a;
}
#define CP_ASYNC16(dst, src) \
    asm volatile("cp.async.cg.shared.global [%0], [%1], 16;" :: "r"(dst), "l"(src) : "memory")
#define CP_COMMIT() asm volatile("cp.async.commit_group;" ::: "memory")
#define CP_WAIT(n)  asm volatile("cp.async.wait_group %0;" :: "n"(n) : "memory")

#define MMA_F16(c, a, b) \
    asm volatile("mma.sync.aligned.m16n8k16.row.col.f32.f16.f16.f32 " \
        "{%0,%1,%2,%3}, {%4,%5,%6,%7}, {%8,%9}, {%0,%1,%2,%3};" \
        : "+f"((c)[0]), "+f"((c)[1]), "+f"((c)[2]), "+f"((c)[3]) \
        : "r"((a)[0]), "r"((a)[1]), "r"((a)[2]), "r"((a)[3]), \
          "r"((b)[0]), "r"((b)[1]))

#define LDSM_X4(r, addr) \
    asm volatile("ldmatrix.sync.aligned.m8n8.x4.shared.b16 {%0,%1,%2,%3}, [%4];" \
        : "=r"((r)[0]), "=r"((r)[1]), "=r"((r)[2]), "=r"((r)[3]) : "r"(addr))

// ---------------------------------------------------------------------------
// coeff kernel
// ---------------------------------------------------------------------------
__global__ void coeff_kernel(const float* __restrict__ taus) {
    int t = threadIdx.x;
    if (t >= NCOEF * NFILT) return;
    int k = t / NFILT, f = t % NFILT;
    double tau = (double)taus[f];
    double s = 0.0;
    for (int j = 0; j < NCOEF; ++j) {
        double jj = (double)j + 0.5;
        double pt = cos(PI * jj / (double)NCOEF) + 1.0;
        s += cos(PI * (double)k * jj / (double)NCOEF) * exp(-pt * tau);
    }
    g_c[k * NFILT + f] = (float)(s * 2.0 / (double)NCOEF);
}

// ---------------------------------------------------------------------------
// init: T0 = I, T1 = M = L - I (fp32 archive), MH/ML fp16 split of M
// ---------------------------------------------------------------------------
__global__ void init_split_kernel(const float* __restrict__ L) {
    size_t base = ((size_t)blockIdx.x * blockDim.x + threadIdx.x) * 4;
    if (base >= NN) return;
    size_t row = base / N, col0 = base % N;
    float4 v = *reinterpret_cast<const float4*>(L + base);
    float4 id = make_float4(0.f, 0.f, 0.f, 0.f);
    if (row >= col0 && row < col0 + 4) (&id.x)[row - col0] = 1.0f;
    float4 m = make_float4(v.x - id.x, v.y - id.y, v.z - id.z, v.w - id.w);
    *reinterpret_cast<float4*>(&g_scratch[base])      = id;
    *reinterpret_cast<float4*>(&g_scratch[NN + base]) = m;

    __half h[4], l[4];
    #pragma unroll
    for (int i = 0; i < 4; ++i) {
        float x = (&m.x)[i];
        h[i] = __float2half_rn(x);
        l[i] = __float2half_rn(x - __half2float(h[i]));
    }
    *reinterpret_cast<half2*>(&g_half[HOFF_MH + base])     = __halves2half2(h[0], h[1]);
    *reinterpret_cast<half2*>(&g_half[HOFF_MH + base + 2]) = __halves2half2(h[2], h[3]);
    *reinterpret_cast<half2*>(&g_half[HOFF_ML + base])     = __halves2half2(l[0], l[1]);
    *reinterpret_cast<half2*>(&g_half[HOFF_ML + base + 2]) = __halves2half2(l[2], l[3]);
}

// ---------------------------------------------------------------------------
// 3xFP16 GEMM step on UPPER-TRIANGULAR block set (C is symmetric).
// BM=BN=128, BK=32, 512 threads (16 warps 4x4), warp tile 32x32.
// 4-stage cp.async pipeline, ONE barrier per iter, term-major MMA order.
// Mirror lower triangle via smem-staged transposed write.
// writeHL=0 on the final step (H/L outputs unused) skips fp16 stores.
// ---------------------------------------------------------------------------
constexpr int BM = 128;
constexpr int BK = 32;
constexpr int NITER = N / BK;                  // 64
constexpr int RS    = 40;                      // halves per smem row
constexpr uint32_t TILE_BYTES  = 128 * RS * 2; // 10240
constexpr uint32_t STAGE_BYTES = 4 * TILE_BYTES;     // 40960
constexpr uint32_t SMEM_BYTES  = 4 * STAGE_BYTES;    // 163840
constexpr int RS2 = 129;                       // floats per staged row (transpose)

__global__ __launch_bounds__(512, 1) void cheb_gemm(
    const __half* __restrict__ Ahi_g, const __half* __restrict__ Alo_g,
    const __half* __restrict__ Bhi_g, const __half* __restrict__ Blo_g,
    const float*  __restrict__ Told,  float* __restrict__ Tout,
    __half* __restrict__ Hout,        __half* __restrict__ Lout,
    int writeHL)
{
    extern __shared__ __align__(16) char smem[];
    const uint32_t sbase = smem_to_u32(smem);
    const int tid  = threadIdx.x;
    const int wid  = tid >> 5;
    const int lane = tid & 31;

    // triangular block decode: 136 blocks, i<=j
    int bid = blockIdx.x;
    int bi = 0;
    while (bid >= 16 - bi) { bid -= 16 - bi; ++bi; }
    const int bj = bi + bid;
    const int brow = bi * BM;
    const int bcol = bj * BM;

    const int wm = (wid >> 2) * 32;    // warp m origin
    const int wn = (wid & 3) * 32;     // warp n origin
    const int gid = lane >> 2;
    const int tig = lane & 3;

    // ldmatrix lane addressing (byte offsets within a tile)
    const uint32_t aoff = (uint32_t)((wm + (lane & 15)) * RS + ((lane >> 4) << 3)) * 2;
    const uint32_t boff = (uint32_t)((wn + ((lane >> 4) << 3) + (lane & 7)) * RS
                                     + (((lane >> 3) & 1) << 3)) * 2;

    // prefetch: 4 tiles x 512 chunks(16B); 1 chunk/tile/thread
    auto prefetch = [&](int it, int s) {
        const int k0 = it * BK;
        const uint32_t st = sbase + (uint32_t)s * STAGE_BYTES;
        const int r  = tid >> 2;
        const int c4 = tid & 3;
        const uint32_t so = (uint32_t)(r * RS + c4 * 8) * 2;
        const size_t ga = (size_t)(brow + r) * N + k0 + c4 * 8;
        const size_t gb = (size_t)(bcol + r) * N + k0 + c4 * 8;   // symmetric B
        CP_ASYNC16(st + 0 * TILE_BYTES + so, Ahi_g + ga);
        CP_ASYNC16(st + 1 * TILE_BYTES + so, Alo_g + ga);
        CP_ASYNC16(st + 2 * TILE_BYTES + so, Bhi_g + gb);
        CP_ASYNC16(st + 3 * TILE_BYTES + so, Blo_g + gb);
        CP_COMMIT();
    };

    float acc[2][4][4];
    #pragma unroll
    for (int mt = 0; mt < 2; ++mt)
        #pragma unroll
        for (int nt = 0; nt < 4; ++nt)
            acc[mt][nt][0] = acc[mt][nt][1] = acc[mt][nt][2] = acc[mt][nt][3] = 0.f;

    prefetch(0, 0);
    prefetch(1, 1);
    prefetch(2, 2);

    for (int it = 0; it < NITER; ++it) {
        const int s = it & 3;
        const int rem = NITER - 1 - it;
        if (rem >= 2)      { CP_WAIT(2); }
        else if (rem == 1) { CP_WAIT(1); }
        else               { CP_WAIT(0); }
        __syncthreads();
        // prefetch target (s+3)&3 was last READ at iter it-1; safe after barrier.
        if (it + 3 < NITER) prefetch(it + 3, (it + 3) & 3);

        const uint32_t st = sbase + (uint32_t)s * STAGE_BYTES;
        #pragma unroll
        for (int kk = 0; kk < 2; ++kk) {
            const uint32_t kb = (uint32_t)(kk * 16 * 2);
            uint32_t ah[2][4], al[2][4], bh[2][4], bl[2][4];
            #pragma unroll
            for (int mt = 0; mt < 2; ++mt) {
                const uint32_t a0 = st + aoff + (uint32_t)(mt * 16 * RS * 2) + kb;
                LDSM_X4(ah[mt], a0 + 0 * TILE_BYTES);
                LDSM_X4(al[mt], a0 + 1 * TILE_BYTES);
            }
            #pragma unroll
            for (int p = 0; p < 2; ++p) {
                const uint32_t b0 = st + boff + (uint32_t)(p * 16 * RS * 2) + kb;
                LDSM_X4(bh[p], b0 + 2 * TILE_BYTES);
                LDSM_X4(bl[p], b0 + 3 * TILE_BYTES);
            }
            // term-major order: 8 independent MMAs between same-acc reuses
            #pragma unroll
            for (int mt = 0; mt < 2; ++mt)
                #pragma unroll
                for (int nt = 0; nt < 4; ++nt)
                    MMA_F16(acc[mt][nt], ah[mt], &bh[nt >> 1][(nt & 1) * 2]);
            #pragma unroll
            for (int mt = 0; mt < 2; ++mt)
                #pragma unroll
                for (int nt = 0; nt < 4; ++nt)
                    MMA_F16(acc[mt][nt], ah[mt], &bl[nt >> 1][(nt & 1) * 2]);
            #pragma unroll
            for (int mt = 0; mt < 2; ++mt)
                #pragma unroll
                for (int nt = 0; nt < 4; ++nt)
                    MMA_F16(acc[mt][nt], al[mt], &bh[nt >> 1][(nt & 1) * 2]);
        }
    }
    __syncthreads();   // mainloop smem reads done before epilogue reuses smem

    // ---------------- epilogue ----------------
    float* stagef = reinterpret_cast<float*>(smem);   // 128 x 129 floats

    #pragma unroll
    for (int mt = 0; mt < 2; ++mt) {
        #pragma unroll
        for (int nt = 0; nt < 4; ++nt) {
            const int cl = wn + nt * 8 + 2 * tig;
            #pragma unroll
            for (int h = 0; h < 2; ++h) {
                const int rl = wm + mt * 16 + gid + h * 8;
                const size_t gi = (size_t)(brow + rl) * N + bcol + cl;
                float2 to = *reinterpret_cast<const float2*>(Told + gi);
                float2 t;
                t.x = 2.0f * acc[mt][nt][2 * h]     - to.x;
                t.y = 2.0f * acc[mt][nt][2 * h + 1] - to.y;
                *reinterpret_cast<float2*>(Tout + gi) = t;
                if (writeHL) {
                    __half hx = __float2half_rn(t.x);
                    __half hy = __float2half_rn(t.y);
                    __half lx = __float2half_rn(t.x - __half2float(hx));
                    __half ly = __float2half_rn(t.y - __half2float(hy));
                    *reinterpret_cast<half2*>(Hout + gi) = __halves2half2(hx, hy);
                    *reinterpret_cast<half2*>(Lout + gi) = __halves2half2(lx, ly);
                }
                stagef[rl * RS2 + cl]     = t.x;
                stagef[rl * RS2 + cl + 1] = t.y;
            }
        }
    }

    if (bj > bi) {
        __syncthreads();
        // mirror: out[(bcol+c)][brow+r] = t[r][c]
        #pragma unroll
        for (int q8 = 0; q8 < 8; ++q8) {
            const int c = wid * 8 + q8;
            const size_t obase = (size_t)(bcol + c) * N + brow;
            #pragma unroll
            for (int q = 0; q < 4; ++q) {
                const int r = q * 32 + lane;
                float t = stagef[r * RS2 + c];
                Tout[obase + r] = t;
                if (writeHL) {
                    __half hx = __float2half_rn(t);
                    __half lx = __float2half_rn(t - __half2float(hx));
                    Hout[obase + r] = hx;
                    Lout[obase + r] = lx;
                }
            }
        }
    }
}

// ---------------------------------------------------------------------------
// final reduction: out[f*N + i, j] = sum_k chat[k,f] * T_k[i,j]
// T_0 = I handled analytically (diagonal add of 0.5*c0); planes 1..16 read
// with streaming hints (no reuse), output written streaming.
// ---------------------------------------------------------------------------
__global__ __launch_bounds__(256) void reduce_kernel(float* __restrict__ out) {
    __shared__ float sc[NCOEF * NFILT];
    if (threadIdx.x < NCOEF * NFILT) {
        float v = g_c[threadIdx.x];
        if (threadIdx.x < NFILT) v *= 0.5f;   // k == 0 entries
        sc[threadIdx.x] = v;
    }
    __syncthreads();

    size_t base = ((size_t)blockIdx.x * blockDim.x + threadIdx.x) * 4;
    if (base >= NN) return;
    const size_t row  = base / N;
    const size_t col0 = base % N;

    float acc[NFILT][4];
    #pragma unroll
    for (int f = 0; f < NFILT; ++f)
        acc[f][0] = acc[f][1] = acc[f][2] = acc[f][3] = 0.f;

    // T_0 = I: diagonal contribution only
    if (row >= col0 && row < col0 + 4) {
        const int d = (int)(row - col0);
        #pragma unroll
        for (int f = 0; f < NFILT; ++f)
            acc[f][d] = sc[f];
    }

    #pragma unroll
    for (int k = 1; k < NCOEF; ++k) {
        float4 t = __ldcs(reinterpret_cast<const float4*>(&g_scratch[(size_t)k * NN + base]));
        #pragma unroll
        for (int f = 0; f < NFILT; ++f) {
            float cf = sc[k * NFILT + f];
            acc[f][0] += cf * t.x; acc[f][1] += cf * t.y;
            acc[f][2] += cf * t.z; acc[f][3] += cf * t.w;
        }
    }
    #pragma unroll
    for (int f = 0; f < NFILT; ++f) {
        float4 o = make_float4(acc[f][0], acc[f][1], acc[f][2], acc[f][3]);
        __stcs(reinterpret_cast<float4*>(&out[(size_t)f * NN + base]), o);
    }
}

// ---------------------------------------------------------------------------
// Launch
// ---------------------------------------------------------------------------
extern "C" void kernel_launch(void* const* d_in, const int* in_sizes, int n_in,
                              void* d_out, int out_size) {
    const float* L    = (const float*)d_in[0];
    const float* taus = (const float*)d_in[1];
    float* out = (float*)d_out;

    void* sp = nullptr;
    cudaGetSymbolAddress(&sp, g_scratch);
    float* S = (float*)sp;
    void* hp = nullptr;
    cudaGetSymbolAddress(&hp, g_half);
    __half* H = (__half*)hp;

    static bool attr_set = false;
    if (!attr_set) {
        cudaFuncSetAttribute(cheb_gemm, cudaFuncAttributeMaxDynamicSharedMemorySize, SMEM_BYTES);
        attr_set = true;
    }

    coeff_kernel<<<1, 256>>>(taus);
    const int vec_blocks = (int)(NN / 4 / 256);   // 4096
    init_split_kernel<<<vec_blocks, 256>>>(L);

    const int NB = 136;   // 16*17/2 upper-triangular blocks
    for (int k = 2; k < NCOEF; ++k) {
        const __half* bh = (k == 2) ? H + HOFF_MH : (((k - 1) & 1) ? H + HOFF_H1 : H + HOFF_H0);
        const __half* bl = (k == 2) ? H + HOFF_ML : (((k - 1) & 1) ? H + HOFF_L1 : H + HOFF_L0);
        __half* ho = (k & 1) ? H + HOFF_H1 : H + HOFF_H0;
        __half* lo = (k & 1) ? H + HOFF_L1 : H + HOFF_L0;
        const int writeHL = (k < NCOEF - 1) ? 1 : 0;   // last step's H/L unused
        cheb_gemm<<<NB, 512, SMEM_BYTES>>>(
            H + HOFF_MH, H + HOFF_ML, bh, bl,
            S + (size_t)(k - 2) * NN, S + (size_t)k * NN, ho, lo, writeHL);
    }

    reduce_kernel<<<vec_blocks, 256>>>(out);
}

// round 15
// speedup vs baseline: 1.0146x; 1.0146x over previous
#include <cuda_runtime.h>
#include <cuda_fp16.h>
#include <cstdint>
#include <cstddef>

// Problem constants (fixed: N_VERT=2048, NF=8, order=16, LMAX=2 -> a1=a2=1)
constexpr int    N      = 2048;
constexpr size_t NN     = (size_t)N * N;
constexpr int    NFILT  = 8;
constexpr int    NCOEF  = 17;
constexpr double PI     = 3.14159265358979323846;

// fp32 archive T_0..T_16 (for the final reduction)
__device__ float  g_scratch[(size_t)17 * NN];
// fp16 hi/lo operand arrays: MH | ML | H0 | L0 | H1 | L1
constexpr size_t HOFF_MH = 0;
constexpr size_t HOFF_ML = NN;
constexpr size_t HOFF_H0 = 2 * NN;
constexpr size_t HOFF_L0 = 3 * NN;
constexpr size_t HOFF_H1 = 4 * NN;
constexpr size_t HOFF_L1 = 5 * NN;
__device__ __half g_half[(size_t)6 * NN];
__device__ float  g_c[NCOEF * NFILT];

// ---------------------------------------------------------------------------
// helpers
// ---------------------------------------------------------------------------
__device__ __forceinline__ uint32_t smem_to_u32(const void* p) {
    uint32_t a;
    asm("{ .reg .u64 t; cvta.to.shared.u64 t, %1; cvt.u32.u64 %0, t; }" : "=r"(a) : "l"(p));
    return a;
}
#define CP_ASYNC16(dst, src) \
    asm volatile("cp.async.cg.shared.global [%0], [%1], 16;" :: "r"(dst), "l"(src) : "memory")
#define CP_COMMIT() asm volatile("cp.async.commit_group;" ::: "memory")
#define CP_WAIT(n)  asm volatile("cp.async.wait_group %0;" :: "n"(n) : "memory")

#define MMA_F16(c, a, b) \
    asm volatile("mma.sync.aligned.m16n8k16.row.col.f32.f16.f16.f32 " \
        "{%0,%1,%2,%3}, {%4,%5,%6,%7}, {%8,%9}, {%0,%1,%2,%3};" \
        : "+f"((c)[0]), "+f"((c)[1]), "+f"((c)[2]), "+f"((c)[3]) \
        : "r"((a)[0]), "r"((a)[1]), "r"((a)[2]), "r"((a)[3]), \
          "r"((b)[0]), "r"((b)[1]))

#define LDSM_X4(r, addr) \
    asm volatile("ldmatrix.sync.aligned.m8n8.x4.shared.b16 {%0,%1,%2,%3}, [%4];" \
        : "=r"((r)[0]), "=r"((r)[1]), "=r"((r)[2]), "=r"((r)[3]) : "r"(addr))

// ---------------------------------------------------------------------------
// coeff kernel
// ---------------------------------------------------------------------------
__global__ void coeff_kernel(const float* __restrict__ taus) {
    int t = threadIdx.x;
    if (t >= NCOEF * NFILT) return;
    int k = t / NFILT, f = t % NFILT;
    double tau = (double)taus[f];
    double s = 0.0;
    for (int j = 0; j < NCOEF; ++j) {
        double jj = (double)j + 0.5;
        double pt = cos(PI * jj / (double)NCOEF) + 1.0;
        s += cos(PI * (double)k * jj / (double)NCOEF) * exp(-pt * tau);
    }
    g_c[k * NFILT + f] = (float)(s * 2.0 / (double)NCOEF);
}

// ---------------------------------------------------------------------------
// init: T0 = I, T1 = M = L - I (fp32 archive), MH/ML fp16 split of M
// ---------------------------------------------------------------------------
__global__ void init_split_kernel(const float* __restrict__ L) {
    size_t base = ((size_t)blockIdx.x * blockDim.x + threadIdx.x) * 4;
    if (base >= NN) return;
    size_t row = base / N, col0 = base % N;
    float4 v = *reinterpret_cast<const float4*>(L + base);
    float4 id = make_float4(0.f, 0.f, 0.f, 0.f);
    if (row >= col0 && row < col0 + 4) (&id.x)[row - col0] = 1.0f;
    float4 m = make_float4(v.x - id.x, v.y - id.y, v.z - id.z, v.w - id.w);
    *reinterpret_cast<float4*>(&g_scratch[base])      = id;
    *reinterpret_cast<float4*>(&g_scratch[NN + base]) = m;

    __half h[4], l[4];
    #pragma unroll
    for (int i = 0; i < 4; ++i) {
        float x = (&m.x)[i];
        h[i] = __float2half_rn(x);
        l[i] = __float2half_rn(x - __half2float(h[i]));
    }
    *reinterpret_cast<half2*>(&g_half[HOFF_MH + base])     = __halves2half2(h[0], h[1]);
    *reinterpret_cast<half2*>(&g_half[HOFF_MH + base + 2]) = __halves2half2(h[2], h[3]);
    *reinterpret_cast<half2*>(&g_half[HOFF_ML + base])     = __halves2half2(l[0], l[1]);
    *reinterpret_cast<half2*>(&g_half[HOFF_ML + base + 2]) = __halves2half2(l[2], l[3]);
}

// ---------------------------------------------------------------------------
// 3xFP16 GEMM step on UPPER-TRIANGULAR block set (C is symmetric).
// BM=BN=128, BK=32, 512 threads (16 warps 4x4), warp tile 32x32.
// 4-stage cp.async pipeline, ONE barrier per iter, term-major MMA order.
// Mirror lower triangle via smem-staged transposed write.
// WRITEHL is a TEMPLATE param: the =1 instantiation is byte-identical to the
// round-6 best kernel (regs 96); =0 (final step) drops unused fp16 stores.
// ---------------------------------------------------------------------------
constexpr int BM = 128;
constexpr int BK = 32;
constexpr int NITER = N / BK;                  // 64
constexpr int RS    = 40;                      // halves per smem row
constexpr uint32_t TILE_BYTES  = 128 * RS * 2; // 10240
constexpr uint32_t STAGE_BYTES = 4 * TILE_BYTES;     // 40960
constexpr uint32_t SMEM_BYTES  = 4 * STAGE_BYTES;    // 163840
constexpr int RS2 = 129;                       // floats per staged row (transpose)

template <int WRITEHL>
__global__ __launch_bounds__(512, 1) void cheb_gemm(
    const __half* __restrict__ Ahi_g, const __half* __restrict__ Alo_g,
    const __half* __restrict__ Bhi_g, const __half* __restrict__ Blo_g,
    const float*  __restrict__ Told,  float* __restrict__ Tout,
    __half* __restrict__ Hout,        __half* __restrict__ Lout)
{
    extern __shared__ __align__(16) char smem[];
    const uint32_t sbase = smem_to_u32(smem);
    const int tid  = threadIdx.x;
    const int wid  = tid >> 5;
    const int lane = tid & 31;

    // triangular block decode: 136 blocks, i<=j
    int bid = blockIdx.x;
    int bi = 0;
    while (bid >= 16 - bi) { bid -= 16 - bi; ++bi; }
    const int bj = bi + bid;
    const int brow = bi * BM;
    const int bcol = bj * BM;

    const int wm = (wid >> 2) * 32;    // warp m origin
    const int wn = (wid & 3) * 32;     // warp n origin
    const int gid = lane >> 2;
    const int tig = lane & 3;

    // ldmatrix lane addressing (byte offsets within a tile)
    const uint32_t aoff = (uint32_t)((wm + (lane & 15)) * RS + ((lane >> 4) << 3)) * 2;
    const uint32_t boff = (uint32_t)((wn + ((lane >> 4) << 3) + (lane & 7)) * RS
                                     + (((lane >> 3) & 1) << 3)) * 2;

    // prefetch: 4 tiles x 512 chunks(16B); 1 chunk/tile/thread
    auto prefetch = [&](int it, int s) {
        const int k0 = it * BK;
        const uint32_t st = sbase + (uint32_t)s * STAGE_BYTES;
        const int r  = tid >> 2;
        const int c4 = tid & 3;
        const uint32_t so = (uint32_t)(r * RS + c4 * 8) * 2;
        const size_t ga = (size_t)(brow + r) * N + k0 + c4 * 8;
        const size_t gb = (size_t)(bcol + r) * N + k0 + c4 * 8;   // symmetric B
        CP_ASYNC16(st + 0 * TILE_BYTES + so, Ahi_g + ga);
        CP_ASYNC16(st + 1 * TILE_BYTES + so, Alo_g + ga);
        CP_ASYNC16(st + 2 * TILE_BYTES + so, Bhi_g + gb);
        CP_ASYNC16(st + 3 * TILE_BYTES + so, Blo_g + gb);
        CP_COMMIT();
    };

    float acc[2][4][4];
    #pragma unroll
    for (int mt = 0; mt < 2; ++mt)
        #pragma unroll
        for (int nt = 0; nt < 4; ++nt)
            acc[mt][nt][0] = acc[mt][nt][1] = acc[mt][nt][2] = acc[mt][nt][3] = 0.f;

    prefetch(0, 0);
    prefetch(1, 1);
    prefetch(2, 2);

    for (int it = 0; it < NITER; ++it) {
        const int s = it & 3;
        const int rem = NITER - 1 - it;
        if (rem >= 2)      { CP_WAIT(2); }
        else if (rem == 1) { CP_WAIT(1); }
        else               { CP_WAIT(0); }
        __syncthreads();
        // prefetch target (s+3)&3 was last READ at iter it-1; safe after barrier.
        if (it + 3 < NITER) prefetch(it + 3, (it + 3) & 3);

        const uint32_t st = sbase + (uint32_t)s * STAGE_BYTES;
        #pragma unroll
        for (int kk = 0; kk < 2; ++kk) {
            const uint32_t kb = (uint32_t)(kk * 16 * 2);
            uint32_t ah[2][4], al[2][4], bh[2][4], bl[2][4];
            #pragma unroll
            for (int mt = 0; mt < 2; ++mt) {
                const uint32_t a0 = st + aoff + (uint32_t)(mt * 16 * RS * 2) + kb;
                LDSM_X4(ah[mt], a0 + 0 * TILE_BYTES);
                LDSM_X4(al[mt], a0 + 1 * TILE_BYTES);
            }
            #pragma unroll
            for (int p = 0; p < 2; ++p) {
                const uint32_t b0 = st + boff + (uint32_t)(p * 16 * RS * 2) + kb;
                LDSM_X4(bh[p], b0 + 2 * TILE_BYTES);
                LDSM_X4(bl[p], b0 + 3 * TILE_BYTES);
            }
            // term-major order: 8 independent MMAs between same-acc reuses
            #pragma unroll
            for (int mt = 0; mt < 2; ++mt)
                #pragma unroll
                for (int nt = 0; nt < 4; ++nt)
                    MMA_F16(acc[mt][nt], ah[mt], &bh[nt >> 1][(nt & 1) * 2]);
            #pragma unroll
            for (int mt = 0; mt < 2; ++mt)
                #pragma unroll
                for (int nt = 0; nt < 4; ++nt)
                    MMA_F16(acc[mt][nt], ah[mt], &bl[nt >> 1][(nt & 1) * 2]);
            #pragma unroll
            for (int mt = 0; mt < 2; ++mt)
                #pragma unroll
                for (int nt = 0; nt < 4; ++nt)
                    MMA_F16(acc[mt][nt], al[mt], &bh[nt >> 1][(nt & 1) * 2]);
        }
    }
    __syncthreads();   // mainloop smem reads done before epilogue reuses smem

    // ---------------- epilogue ----------------
    float* stagef = reinterpret_cast<float*>(smem);   // 128 x 129 floats

    #pragma unroll
    for (int mt = 0; mt < 2; ++mt) {
        #pragma unroll
        for (int nt = 0; nt < 4; ++nt) {
            const int cl = wn + nt * 8 + 2 * tig;
            #pragma unroll
            for (int h = 0; h < 2; ++h) {
                const int rl = wm + mt * 16 + gid + h * 8;
                const size_t gi = (size_t)(brow + rl) * N + bcol + cl;
                float2 to = *reinterpret_cast<const float2*>(Told + gi);
                float2 t;
                t.x = 2.0f * acc[mt][nt][2 * h]     - to.x;
                t.y = 2.0f * acc[mt][nt][2 * h + 1] - to.y;
                *reinterpret_cast<float2*>(Tout + gi) = t;
                if (WRITEHL) {
                    __half hx = __float2half_rn(t.x);
                    __half hy = __float2half_rn(t.y);
                    __half lx = __float2half_rn(t.x - __half2float(hx));
                    __half ly = __float2half_rn(t.y - __half2float(hy));
                    *reinterpret_cast<half2*>(Hout + gi) = __halves2half2(hx, hy);
                    *reinterpret_cast<half2*>(Lout + gi) = __halves2half2(lx, ly);
                }
                stagef[rl * RS2 + cl]     = t.x;
                stagef[rl * RS2 + cl + 1] = t.y;
            }
        }
    }

    if (bj > bi) {
        __syncthreads();
        // mirror: out[(bcol+c)][brow+r] = t[r][c]
        #pragma unroll
        for (int q8 = 0; q8 < 8; ++q8) {
            const int c = wid * 8 + q8;
            const size_t obase = (size_t)(bcol + c) * N + brow;
            #pragma unroll
            for (int q = 0; q < 4; ++q) {
                const int r = q * 32 + lane;
                float t = stagef[r * RS2 + c];
                Tout[obase + r] = t;
                if (WRITEHL) {
                    __half hx = __float2half_rn(t);
                    __half lx = __float2half_rn(t - __half2float(hx));
                    Hout[obase + r] = hx;
                    Lout[obase + r] = lx;
                }
            }
        }
    }
}

// ---------------------------------------------------------------------------
// final reduction: out[f*N + i, j] = sum_k chat[k,f] * T_k[i,j]
// T_0 = I handled analytically (diagonal add of 0.5*c0); planes 1..16 read
// with streaming hints (no reuse), output written streaming.
// ---------------------------------------------------------------------------
__global__ __launch_bounds__(256) void reduce_kernel(float* __restrict__ out) {
    __shared__ float sc[NCOEF * NFILT];
    if (threadIdx.x < NCOEF * NFILT) {
        float v = g_c[threadIdx.x];
        if (threadIdx.x < NFILT) v *= 0.5f;   // k == 0 entries
        sc[threadIdx.x] = v;
    }
    __syncthreads();

    size_t base = ((size_t)blockIdx.x * blockDim.x + threadIdx.x) * 4;
    if (base >= NN) return;
    const size_t row  = base / N;
    const size_t col0 = base % N;

    float acc[NFILT][4];
    #pragma unroll
    for (int f = 0; f < NFILT; ++f)
        acc[f][0] = acc[f][1] = acc[f][2] = acc[f][3] = 0.f;

    // T_0 = I: diagonal contribution only
    if (row >= col0 && row < col0 + 4) {
        const int d = (int)(row - col0);
        #pragma unroll
        for (int f = 0; f < NFILT; ++f)
            acc[f][d] = sc[f];
    }

    #pragma unroll
    for (int k = 1; k < NCOEF; ++k) {
        float4 t = __ldcs(reinterpret_cast<const float4*>(&g_scratch[(size_t)k * NN + base]));
        #pragma unroll
        for (int f = 0; f < NFILT; ++f) {
            float cf = sc[k * NFILT + f];
            acc[f][0] += cf * t.x; acc[f][1] += cf * t.y;
            acc[f][2] += cf * t.z; acc[f][3] += cf * t.w;
        }
    }
    #pragma unroll
    for (int f = 0; f < NFILT; ++f) {
        float4 o = make_float4(acc[f][0], acc[f][1], acc[f][2], acc[f][3]);
        __stcs(reinterpret_cast<float4*>(&out[(size_t)f * NN + base]), o);
    }
}

// ---------------------------------------------------------------------------
// Launch
// ---------------------------------------------------------------------------
extern "C" void kernel_launch(void* const* d_in, const int* in_sizes, int n_in,
                              void* d_out, int out_size) {
    const float* L    = (const float*)d_in[0];
    const float* taus = (const float*)d_in[1];
    float* out = (float*)d_out;

    void* sp = nullptr;
    cudaGetSymbolAddress(&sp, g_scratch);
    float* S = (float*)sp;
    void* hp = nullptr;
    cudaGetSymbolAddress(&hp, g_half);
    __half* H = (__half*)hp;

    static bool attr_set = false;
    if (!attr_set) {
        cudaFuncSetAttribute(cheb_gemm<1>, cudaFuncAttributeMaxDynamicSharedMemorySize, SMEM_BYTES);
        cudaFuncSetAttribute(cheb_gemm<0>, cudaFuncAttributeMaxDynamicSharedMemorySize, SMEM_BYTES);
        attr_set = true;
    }

    coeff_kernel<<<1, 256>>>(taus);
    const int vec_blocks = (int)(NN / 4 / 256);   // 4096
    init_split_kernel<<<vec_blocks, 256>>>(L);

    const int NB = 136;   // 16*17/2 upper-triangular blocks
    for (int k = 2; k < NCOEF; ++k) {
        const __half* bh = (k == 2) ? H + HOFF_MH : (((k - 1) & 1) ? H + HOFF_H1 : H + HOFF_H0);
        const __half* bl = (k == 2) ? H + HOFF_ML : (((k - 1) & 1) ? H + HOFF_L1 : H + HOFF_L0);
        __half* ho = (k & 1) ? H + HOFF_H1 : H + HOFF_H0;
        __half* lo = (k & 1) ? H + HOFF_L1 : H + HOFF_L0;
        if (k < NCOEF - 1) {
            cheb_gemm<1><<<NB, 512, SMEM_BYTES>>>(
                H + HOFF_MH, H + HOFF_ML, bh, bl,
                S + (size_t)(k - 2) * NN, S + (size_t)k * NN, ho, lo);
        } else {
            cheb_gemm<0><<<NB, 512, SMEM_BYTES>>>(
                H + HOFF_MH, H + HOFF_ML, bh, bl,
                S + (size_t)(k - 2) * NN, S + (size_t)k * NN, ho, lo);
        }
    }

    reduce_kernel<<<vec_blocks, 256>>>(out);
}